// round 9
// baseline (speedup 1.0000x reference)
#include <cuda_runtime.h>

// MultiIndexSelect: out[to_k[i]] = mat_k[from_k[i]], k=0..2, L=400000 rows, D=64 f32.
// Row = 256 B = 16 float4 slots. UNROLL=8 slots/thread, all index loads + gathers
// batched (predicated, single path — same structure as the R4 pass) before the
// stores. R4 (UNROLL=4): 97us, DRAM 66.2%, latency-bound -> double MLP.

static constexpr int UNROLL = 8;

__global__ __launch_bounds__(256) void multi_index_select_kernel(
    const float4* __restrict__ m0,
    const float4* __restrict__ m1,
    const float4* __restrict__ m2,
    const int* __restrict__ f0,
    const int* __restrict__ f1,
    const int* __restrict__ f2,
    const int* __restrict__ t0,
    const int* __restrict__ t1,
    const int* __restrict__ t2,
    float4* __restrict__ out,
    int L)
{
    const unsigned total = 3u * (unsigned)L * 16u;     // 19.2M slots
    const unsigned base  = blockIdx.x * (blockDim.x * UNROLL) + threadIdx.x;

    float4   val[UNROLL];
    unsigned dslot[UNROLL];
    bool     ok[UNROLL];

    #pragma unroll
    for (int u = 0; u < UNROLL; u++) {
        unsigned tid = base + u * blockDim.x;
        ok[u] = (tid < total);
        unsigned row  = tid >> 4;
        unsigned lane = tid & 15u;
        if (ok[u]) {
            const float4* __restrict__ mat;
            int src, dst;
            if (row < (unsigned)L) {
                mat = m0; src = __ldg(&f0[row]);        dst = __ldg(&t0[row]);
            } else if (row < 2u * (unsigned)L) {
                unsigned r = row - (unsigned)L;
                mat = m1; src = __ldg(&f1[r]);          dst = __ldg(&t1[r]);
            } else {
                unsigned r = row - 2u * (unsigned)L;
                mat = m2; src = __ldg(&f2[r]);          dst = __ldg(&t2[r]);
            }
            dslot[u] = (unsigned)dst * 16u + lane;
            val[u]   = __ldcs(&mat[(size_t)src * 16u + lane]);  // one-touch: evict-first
        }
    }

    #pragma unroll
    for (int u = 0; u < UNROLL; u++) {
        if (ok[u]) __stcs(&out[dslot[u]], val[u]);
    }
}

extern "C" void kernel_launch(void* const* d_in, const int* in_sizes, int n_in,
                              void* d_out, int out_size)
{
    const float4* m0 = (const float4*)d_in[0];
    const float4* m1 = (const float4*)d_in[1];
    const float4* m2 = (const float4*)d_in[2];
    const int* f0 = (const int*)d_in[3];
    const int* f1 = (const int*)d_in[4];
    const int* f2 = (const int*)d_in[5];
    const int* t0 = (const int*)d_in[6];
    const int* t1 = (const int*)d_in[7];
    const int* t2 = (const int*)d_in[8];

    int L = in_sizes[3];                                // 400000
    unsigned total = 3u * (unsigned)L * 16u;
    int threads = 256;
    unsigned per_block = threads * UNROLL;
    unsigned blocks = (total + per_block - 1) / per_block;   // 9375 exact for L=400000

    multi_index_select_kernel<<<blocks, threads>>>(
        m0, m1, m2, f0, f1, f2, t0, t1, t2, (float4*)d_out, L);
}

// round 10
// speedup vs baseline: 1.2008x; 1.2008x over previous
#include <cuda_runtime.h>
#include <cstdint>

// MultiIndexSelect: out[to_k[i]] = mat_k[from_k[i]], k=0..2, L=400000 rows, D=64 f32.
// Row = 256 B = 16 float4 slots. R4 (reg-batched MLP=4): 97us, DRAM 66%. R9 showed
// register-held MLP=8 kills occupancy (regs 62, occ 44%) -> in-flight product flat.
// Fix: cp.async.cg gathers 16B straight into per-thread-private smem slots — zero
// data registers per outstanding load. 8 outstanding gathers/thread at ~87% occ.
// Barrier-free: each thread reads back only its own smem slots after wait_group.

static constexpr int UNROLL  = 8;
static constexpr int THREADS = 256;

__global__ __launch_bounds__(THREADS) void multi_index_select_kernel(
    const float4* __restrict__ m0,
    const float4* __restrict__ m1,
    const float4* __restrict__ m2,
    const int* __restrict__ f0,
    const int* __restrict__ f1,
    const int* __restrict__ f2,
    const int* __restrict__ t0,
    const int* __restrict__ t1,
    const int* __restrict__ t2,
    float4* __restrict__ out,
    int L)
{
    __shared__ float4 buf[THREADS * UNROLL];           // 32 KB: private slot per (thread,u)

    const unsigned total = 3u * (unsigned)L * 16u;     // 19.2M slots
    const unsigned base  = blockIdx.x * (THREADS * UNROLL) + threadIdx.x;

    const unsigned smem_base =
        (unsigned)__cvta_generic_to_shared(buf) + threadIdx.x * 16u;

    unsigned dslot[UNROLL];
    bool     ok[UNROLL];

    // Phase 1: index loads + register-free gathers into smem (single commit group).
    #pragma unroll
    for (int u = 0; u < UNROLL; u++) {
        unsigned tid = base + u * THREADS;
        ok[u] = (tid < total);
        if (ok[u]) {
            unsigned row  = tid >> 4;
            unsigned lane = tid & 15u;
            const float4* __restrict__ mat;
            int src, dst;
            if (row < (unsigned)L) {
                mat = m0; src = __ldg(&f0[row]);        dst = __ldg(&t0[row]);
            } else if (row < 2u * (unsigned)L) {
                unsigned r = row - (unsigned)L;
                mat = m1; src = __ldg(&f1[r]);          dst = __ldg(&t1[r]);
            } else {
                unsigned r = row - 2u * (unsigned)L;
                mat = m2; src = __ldg(&f2[r]);          dst = __ldg(&t2[r]);
            }
            dslot[u] = (unsigned)dst * 16u + lane;
            const float4* gsrc = &mat[(size_t)src * 16u + lane];
            unsigned saddr = smem_base + (unsigned)(u * THREADS) * 16u;
            asm volatile("cp.async.cg.shared.global [%0], [%1], 16;\n"
                         :: "r"(saddr), "l"(gsrc) : "memory");
        }
    }
    asm volatile("cp.async.commit_group;\n" ::: "memory");
    asm volatile("cp.async.wait_group 0;\n"  ::: "memory");

    // Phase 2: read own slots from smem, streaming scatter stores.
    #pragma unroll
    for (int u = 0; u < UNROLL; u++) {
        if (ok[u]) {
            float4 v = buf[u * THREADS + threadIdx.x];
            __stcs(&out[dslot[u]], v);
        }
    }
}

extern "C" void kernel_launch(void* const* d_in, const int* in_sizes, int n_in,
                              void* d_out, int out_size)
{
    const float4* m0 = (const float4*)d_in[0];
    const float4* m1 = (const float4*)d_in[1];
    const float4* m2 = (const float4*)d_in[2];
    const int* f0 = (const int*)d_in[3];
    const int* f1 = (const int*)d_in[4];
    const int* f2 = (const int*)d_in[5];
    const int* t0 = (const int*)d_in[6];
    const int* t1 = (const int*)d_in[7];
    const int* t2 = (const int*)d_in[8];

    int L = in_sizes[3];                                // 400000
    unsigned total = 3u * (unsigned)L * 16u;
    unsigned per_block = THREADS * UNROLL;
    unsigned blocks = (total + per_block - 1) / per_block;   // 9375 exact for L=400000

    multi_index_select_kernel<<<blocks, THREADS>>>(
        m0, m1, m2, f0, f1, f2, t0, t1, t2, (float4*)d_out, L);
}